// round 1
// baseline (speedup 1.0000x reference)
#include <cuda_runtime.h>

#define Bb 4
#define Nn 1280
#define NM 256
#define NSd 1024
#define Cc 768
#define Hh 12
#define Dd 64
#define MEMN 1280
#define LFULL 2560
#define KSEL_S 640
#define KSEL_M 128
#define NT 256

// ---------------- scratch (static device globals; no allocation) ----------------
__device__ float g_q[Bb*Hh*Nn*Dd];
__device__ float g_k[Bb*Hh*Nn*Dd];
__device__ float g_v[Bb*Hh*Nn*Dd];
__device__ float g_qkvlow[Bb*Nn*24];
__device__ float g_idvlow[Bb*NM*8];
__device__ float g_act[Bb*NM*Hh];
__device__ float g_idv[Bb*NM*Cc];
__device__ float g_xo[Bb*Nn*Cc];
__device__ float g_wplow[Bb*Nn*32];

// ---------------- helpers ----------------
__device__ __forceinline__ unsigned fkey(float f){
    unsigned b = __float_as_uint(f);
    return (b & 0x80000000u) ? ~b : (b | 0x80000000u);
}

// Exact top-K selection + softmax weights, block-wide (NT=256 threads).
// On entry: s[0..L) holds scores, vmax = row max. On exit: s[j] = exp(s_j - vmax)
// for the K selected elements (ties broken by lowest index), 0 otherwise.
// Returns sum of selected exps.
template<int L, int KS>
__device__ float topk_softmax_weights(float* s, unsigned* hist, unsigned* sfx,
                                      float* red, unsigned* ssc, float vmax){
    const int tid = threadIdx.x;
    const int CH = L / NT;
    unsigned prefix = 0;
    int need = KS;
    #pragma unroll
    for (int p = 3; p >= 0; p--){
        const int shift = p * 8;
        const unsigned maskhi = (p == 3) ? 0u : (0xFFFFFFFFu << (shift + 8));
        hist[tid] = 0; __syncthreads();
        for (int i = 0; i < CH; i++){
            unsigned key = fkey(s[tid*CH + i]);
            if ((key & maskhi) == prefix) atomicAdd(&hist[(key >> shift) & 0xFFu], 1u);
        }
        __syncthreads();
        // inclusive suffix-sum (Hillis-Steele)
        sfx[tid] = hist[tid]; __syncthreads();
        for (int off = 1; off < 256; off <<= 1){
            unsigned v = sfx[tid] + ((tid + off < 256) ? sfx[tid + off] : 0u);
            __syncthreads(); sfx[tid] = v; __syncthreads();
        }
        unsigned ge = sfx[tid];
        unsigned gt = (tid < 255) ? sfx[tid + 1] : 0u;
        if ((int)ge >= need && (int)gt < need){
            ssc[0] = (unsigned)tid;
            ssc[1] = (unsigned)(need - (int)gt);
        }
        __syncthreads();
        prefix |= (ssc[0] << shift);
        need = (int)ssc[1];
        __syncthreads();
    }
    const unsigned thr = prefix;
    // count-equal prefix scan for stable tie-breaking (lowest index first)
    int cnt = 0;
    for (int i = 0; i < CH; i++) if (fkey(s[tid*CH + i]) == thr) cnt++;
    sfx[tid] = (unsigned)cnt; __syncthreads();
    for (int off = 1; off < 256; off <<= 1){
        unsigned v = sfx[tid] + ((tid >= off) ? sfx[tid - off] : 0u);
        __syncthreads(); sfx[tid] = v; __syncthreads();
    }
    int excl = (int)sfx[tid] - cnt;
    float lsum = 0.f; int rloc = 0;
    for (int i = 0; i < CH; i++){
        int j = tid*CH + i;
        float v = s[j];
        unsigned key = fkey(v);
        bool sel = (key > thr) || (key == thr && (excl + rloc) < need);
        if (key == thr) rloc++;
        float e = sel ? __expf(v - vmax) : 0.f;
        s[j] = e;
        lsum += e;
    }
    red[tid] = lsum; __syncthreads();
    for (int off = 128; off; off >>= 1){
        if (tid < off) red[tid] += red[tid + off];
        __syncthreads();
    }
    float Z = red[0];
    __syncthreads();
    return Z;
}

// ---------------- kernel 1: qkv lora low = x @ qkv_A^T  (B,N,3,8) ----------------
__global__ void k_qkv_low(const float* __restrict__ x, const float* __restrict__ qkvA){
    const int row = blockIdx.x;
    const int tid = threadIdx.x;
    __shared__ float xs[Cc];
    for (int i = tid; i < Cc; i += NT) xs[i] = x[row*Cc + i];
    __syncthreads();
    const int warp = tid >> 5, lane = tid & 31;
    for (int o = warp; o < 24; o += 8){
        const float* a = &qkvA[o*Cc];
        float p = 0.f;
        for (int i = lane; i < Cc; i += 32) p += xs[i] * a[i];
        #pragma unroll
        for (int off = 16; off; off >>= 1) p += __shfl_xor_sync(0xffffffffu, p, off);
        if (lane == 0) g_qkvlow[row*24 + o] = p;
    }
}

// ---------------- shared SGEMM mainloop: out[m,n] = sum_k A[m,k]*W[n,k] ----------------
#define SGEMM_MAIN(Aptr, Wptr, KDIM)                                              \
    __shared__ __align__(16) float As[16*64];                                      \
    __shared__ __align__(16) float Ws[16*64];                                      \
    float acc[4][4];                                                               \
    _Pragma("unroll") for (int i_ = 0; i_ < 4; i_++)                               \
    _Pragma("unroll") for (int j_ = 0; j_ < 4; j_++) acc[i_][j_] = 0.f;            \
    const int tid = threadIdx.x;                                                   \
    const int ty = tid >> 4, tx = tid & 15;                                        \
    const int lr = tid >> 2, lk = (tid & 3) * 4;                                   \
    const int row0 = blockIdx.y * 64, col0 = blockIdx.x * 64;                      \
    for (int kt = 0; kt < KDIM; kt += 16){                                         \
        float4 a4 = *(const float4*)&Aptr[(row0 + lr)*KDIM + kt + lk];             \
        float4 w4 = *(const float4*)&Wptr[(col0 + lr)*KDIM + kt + lk];             \
        __syncthreads();                                                           \
        As[(lk+0)*64 + lr] = a4.x; As[(lk+1)*64 + lr] = a4.y;                      \
        As[(lk+2)*64 + lr] = a4.z; As[(lk+3)*64 + lr] = a4.w;                      \
        Ws[(lk+0)*64 + lr] = w4.x; Ws[(lk+1)*64 + lr] = w4.y;                      \
        Ws[(lk+2)*64 + lr] = w4.z; Ws[(lk+3)*64 + lr] = w4.w;                      \
        __syncthreads();                                                           \
        _Pragma("unroll")                                                          \
        for (int kk = 0; kk < 16; kk++){                                           \
            float4 ra = *(const float4*)&As[kk*64 + ty*4];                         \
            float4 rb = *(const float4*)&Ws[kk*64 + tx*4];                         \
            acc[0][0] += ra.x*rb.x; acc[0][1] += ra.x*rb.y;                        \
            acc[0][2] += ra.x*rb.z; acc[0][3] += ra.x*rb.w;                        \
            acc[1][0] += ra.y*rb.x; acc[1][1] += ra.y*rb.y;                        \
            acc[1][2] += ra.y*rb.z; acc[1][3] += ra.y*rb.w;                        \
            acc[2][0] += ra.z*rb.x; acc[2][1] += ra.z*rb.y;                        \
            acc[2][2] += ra.z*rb.z; acc[2][3] += ra.z*rb.w;                        \
            acc[3][0] += ra.w*rb.x; acc[3][1] += ra.w*rb.y;                        \
            acc[3][2] += ra.w*rb.z; acc[3][3] += ra.w*rb.w;                        \
        }                                                                          \
    }

// ---------------- kernel 2: QKV GEMM + bias + lora + scatter to (B,H,N,D) ----------------
__global__ void k_sgemm_qkv(const float* __restrict__ x, const float* __restrict__ W,
                            const float* __restrict__ bq, const float* __restrict__ qkvB){
    SGEMM_MAIN(x, W, Cc)
    const int g = col0 / Cc;   // 64 | 768 -> whole block in one of q/k/v
    #pragma unroll
    for (int ii = 0; ii < 4; ii++){
        const int m = row0 + ty*4 + ii;
        const int b = m / Nn, n = m % Nn;
        float lw[8];
        #pragma unroll
        for (int r = 0; r < 8; r++) lw[r] = g_qkvlow[m*24 + g*8 + r];
        #pragma unroll
        for (int jj = 0; jj < 4; jj++){
            const int j = col0 + tx*4 + jj;
            const int c = j - g*Cc;
            const float* bv = &qkvB[(g*Cc + c)*8];
            float lora = 0.f;
            #pragma unroll
            for (int r = 0; r < 8; r++) lora += lw[r] * bv[r];
            float val = acc[ii][jj] + bq[j] + 0.125f * lora;
            const int h = c >> 6, d = c & 63;
            const int dst = ((b*Hh + h)*Nn + n)*Dd + d;
            if (g == 0)      g_q[dst] = val * 0.125f;   // q * D^-0.5
            else if (g == 1) g_k[dst] = val;
            else             g_v[dst] = val;
        }
    }
}

// ---------------- kernel 3: ID_K activation + idv lora low ----------------
__global__ void k_id_small(const float* __restrict__ idt, const float* __restrict__ idkA,
                           const float* __restrict__ idvA, const float* __restrict__ Widk,
                           const float* __restrict__ bidk, const float* __restrict__ idkB){
    const int row = blockIdx.x;
    const int tid = threadIdx.x;
    __shared__ float xs[Cc];
    __shared__ float lk[8], dk[12];
    for (int i = tid; i < Cc; i += NT) xs[i] = idt[row*Cc + i];
    __syncthreads();
    const int warp = tid >> 5, lane = tid & 31;
    for (int o = warp; o < 28; o += 8){
        const float* a;
        if (o < 8)       a = &idkA[o*Cc];
        else if (o < 16) a = &idvA[(o - 8)*Cc];
        else             a = &Widk[(o - 16)*Cc];
        float p = 0.f;
        for (int i = lane; i < Cc; i += 32) p += xs[i] * a[i];
        #pragma unroll
        for (int off = 16; off; off >>= 1) p += __shfl_xor_sync(0xffffffffu, p, off);
        if (lane == 0){
            if (o < 8)       lk[o] = p;
            else if (o < 16) g_idvlow[row*8 + (o - 8)] = p;
            else             dk[o - 16] = p;
        }
    }
    __syncthreads();
    if (tid < 12){
        float lo = 0.f;
        #pragma unroll
        for (int r = 0; r < 8; r++) lo += lk[r] * idkB[tid*8 + r];
        float f = dk[tid] + bidk[tid] + 0.125f * lo;
        g_act[row*Hh + tid] = 1.f + tanhf(f);
    }
}

// ---------------- kernel 4: ID_V GEMM ----------------
__global__ void k_sgemm_idv(const float* __restrict__ idt, const float* __restrict__ W,
                            const float* __restrict__ bidv, const float* __restrict__ idvB){
    SGEMM_MAIN(idt, W, Cc)
    #pragma unroll
    for (int ii = 0; ii < 4; ii++){
        const int m = row0 + ty*4 + ii;
        float lw[8];
        #pragma unroll
        for (int r = 0; r < 8; r++) lw[r] = g_idvlow[m*8 + r];
        #pragma unroll
        for (int jj = 0; jj < 4; jj++){
            const int c = col0 + tx*4 + jj;
            const float* bv = &idvB[c*8];
            float lora = 0.f;
            #pragma unroll
            for (int r = 0; r < 8; r++) lora += lw[r] * bv[r];
            g_idv[m*Cc + c] = acc[ii][jj] + bidv[c] + 0.125f * lora;
        }
    }
}

// ---------------- kernel 5: apply identity mods -> k_m_id, v_m_id (into d_out) ----------------
__global__ void k_apply_id(float* __restrict__ kmid, float* __restrict__ vmid){
    const int idx = blockIdx.x * NT + threadIdx.x;   // < B*H*NM*D
    const int d = idx & 63;
    int t = idx >> 6;
    const int m = t % NM; t /= NM;
    const int h = t % Hh; const int b = t / Hh;
    const int src = ((b*Hh + h)*Nn + m)*Dd + d;
    kmid[idx] = g_k[src] * g_act[(b*NM + m)*Hh + h];
    vmid[idx] = g_v[src] + g_idv[(b*NM + m)*Cc + h*Dd + d];
}

// ---------------- kernel 6: mem attention (L=256, top 128) ----------------
__global__ void k_attn_m(const float* __restrict__ kmid, const float* __restrict__ vmid){
    __shared__ float s[NM];
    __shared__ float qrow[Dd];
    __shared__ unsigned hist[256], sfx[256];
    __shared__ float red[256];
    __shared__ unsigned ssc[2];
    const int blk = blockIdx.x;
    const int m = blk % NM;
    const int bh = blk / NM;
    const int b = bh / Hh, h = bh % Hh;
    const int tid = threadIdx.x;
    if (tid < Dd) qrow[tid] = g_q[(bh*Nn + m)*Dd + tid];
    __syncthreads();
    const int warp = tid >> 5, lane = tid & 31;
    float2 q2 = ((const float2*)qrow)[lane];
    float lmax = -1e30f;
    for (int j = warp; j < NM; j += 8){
        float2 k2 = ((const float2*)&kmid[(bh*NM + j)*Dd])[lane];
        float p = q2.x*k2.x + q2.y*k2.y;
        #pragma unroll
        for (int off = 16; off; off >>= 1) p += __shfl_xor_sync(0xffffffffu, p, off);
        if (lane == 0) s[j] = p;
        lmax = fmaxf(lmax, p);
    }
    red[tid] = lmax; __syncthreads();
    for (int off = 128; off; off >>= 1){
        if (tid < off) red[tid] = fmaxf(red[tid], red[tid + off]);
        __syncthreads();
    }
    float vmax = red[0]; __syncthreads();
    float Z = topk_softmax_weights<NM, KSEL_M>(s, hist, sfx, red, ssc, vmax);
    float invZ = 1.f / Z;
    const int grp = tid >> 6, d = tid & 63;
    float accv = 0.f;
    for (int j = grp; j < NM; j += 4){
        float w = s[j];
        if (w != 0.f) accv += w * vmid[(bh*NM + j)*Dd + d];
    }
    __syncthreads();
    red[tid] = accv; __syncthreads();
    if (tid < 64){
        float o = (red[tid] + red[tid+64] + red[tid+128] + red[tid+192]) * invZ;
        g_xo[(b*Nn + m)*Cc + h*Dd + tid] = o;
    }
}

// ---------------- kernel 7: streaming attention (L=2560, top 640) ----------------
__global__ void k_attn_s(const float* __restrict__ memk, const float* __restrict__ memv,
                         const float* __restrict__ vmid){
    __shared__ float s[LFULL];
    __shared__ float qrow[Dd];
    __shared__ unsigned hist[256], sfx[256];
    __shared__ float red[256];
    __shared__ unsigned ssc[2];
    const int blk = blockIdx.x;
    const int qi = blk % NSd;
    const int bh = blk / NSd;
    const int b = bh / Hh, h = bh % Hh;
    const int tid = threadIdx.x;
    const int nq = NM + qi;
    if (tid < Dd) qrow[tid] = g_q[(bh*Nn + nq)*Dd + tid];
    __syncthreads();
    const int warp = tid >> 5, lane = tid & 31;
    float2 q2 = ((const float2*)qrow)[lane];
    float lmax = -1e30f;
    for (int j = warp; j < LFULL; j += 8){
        const float* kr = (j < MEMN) ? &memk[(bh*MEMN + j)*Dd]
                                     : &g_k[(bh*Nn + (j - MEMN))*Dd];
        float2 k2 = ((const float2*)kr)[lane];
        float p = q2.x*k2.x + q2.y*k2.y;
        #pragma unroll
        for (int off = 16; off; off >>= 1) p += __shfl_xor_sync(0xffffffffu, p, off);
        if (lane == 0) s[j] = p;
        lmax = fmaxf(lmax, p);
    }
    red[tid] = lmax; __syncthreads();
    for (int off = 128; off; off >>= 1){
        if (tid < off) red[tid] = fmaxf(red[tid], red[tid + off]);
        __syncthreads();
    }
    float vmax = red[0]; __syncthreads();
    float Z = topk_softmax_weights<LFULL, KSEL_S>(s, hist, sfx, red, ssc, vmax);
    float invZ = 1.f / Z;
    const int grp = tid >> 6, d = tid & 63;
    float accv = 0.f;
    for (int j = grp; j < LFULL; j += 4){
        float w = s[j];
        if (w != 0.f){
            const float* vr;
            if (j < MEMN)            vr = &memv[(bh*MEMN + j)*Dd];
            else if (j < MEMN + NM)  vr = &vmid[(bh*NM + (j - MEMN))*Dd];
            else                     vr = &g_v[(bh*Nn + (j - MEMN))*Dd];
            accv += w * vr[d];
        }
    }
    __syncthreads();
    red[tid] = accv; __syncthreads();
    if (tid < 64){
        float o = (red[tid] + red[tid+64] + red[tid+128] + red[tid+192]) * invZ;
        g_xo[(b*Nn + nq)*Cc + h*Dd + tid] = o;
    }
}

// ---------------- kernel 8a: route softmax + weighted proj-lora lows ----------------
__global__ void k_route(const float* __restrict__ routeW, const float* __restrict__ projA){
    const int row = blockIdx.x;
    const int tid = threadIdx.x;
    __shared__ float xs[Cc];
    __shared__ float lg[4], pl[32], sm[4];
    for (int i = tid; i < Cc; i += NT) xs[i] = g_xo[row*Cc + i];
    __syncthreads();
    const int warp = tid >> 5, lane = tid & 31;
    for (int o = warp; o < 36; o += 8){
        const float* a = (o < 4) ? &routeW[o*Cc] : &projA[(o - 4)*Cc];
        float p = 0.f;
        for (int i = lane; i < Cc; i += 32) p += xs[i] * a[i];
        #pragma unroll
        for (int off = 16; off; off >>= 1) p += __shfl_xor_sync(0xffffffffu, p, off);
        if (lane == 0){
            if (o < 4) lg[o] = p;
            else       pl[o - 4] = p;
        }
    }
    __syncthreads();
    if (tid == 0){
        float mx = fmaxf(fmaxf(lg[0], lg[1]), fmaxf(lg[2], lg[3]));
        float e0 = __expf(lg[0]-mx), e1 = __expf(lg[1]-mx);
        float e2 = __expf(lg[2]-mx), e3 = __expf(lg[3]-mx);
        float si = 1.f / (e0 + e1 + e2 + e3);
        sm[0] = e0*si; sm[1] = e1*si; sm[2] = e2*si; sm[3] = e3*si;
    }
    __syncthreads();
    if (tid < 32) g_wplow[row*32 + tid] = sm[tid >> 3] * pl[tid] * 0.125f;
}

// ---------------- kernel 8b: output projection GEMM + MoE lora ----------------
__global__ void k_sgemm_proj(const float* __restrict__ W, const float* __restrict__ bp,
                             const float* __restrict__ projB, float* __restrict__ out){
    SGEMM_MAIN(g_xo, W, Cc)
    #pragma unroll
    for (int ii = 0; ii < 4; ii++){
        const int m = row0 + ty*4 + ii;
        float wl[32];
        #pragma unroll
        for (int t = 0; t < 32; t++) wl[t] = g_wplow[m*32 + t];
        #pragma unroll
        for (int jj = 0; jj < 4; jj++){
            const int c = col0 + tx*4 + jj;
            float lora = 0.f;
            #pragma unroll
            for (int e = 0; e < 4; e++){
                const float* bv = &projB[(e*Cc + c)*8];
                #pragma unroll
                for (int r = 0; r < 8; r++) lora += wl[e*8 + r] * bv[r];
            }
            out[m*Cc + c] = acc[ii][jj] + bp[c] + lora;
        }
    }
}

// ---------------- launch ----------------
extern "C" void kernel_launch(void* const* d_in, const int* in_sizes, int n_in,
                              void* d_out, int out_size){
    const float* x      = (const float*)d_in[0];
    const float* idt    = (const float*)d_in[1];
    const float* memk   = (const float*)d_in[2];
    const float* memv   = (const float*)d_in[3];
    const float* Wqkv   = (const float*)d_in[4];
    const float* bqkv   = (const float*)d_in[5];
    const float* qkvA   = (const float*)d_in[6];
    const float* qkvB   = (const float*)d_in[7];
    const float* Wproj  = (const float*)d_in[8];
    const float* bproj  = (const float*)d_in[9];
    const float* routeW = (const float*)d_in[10];
    const float* projA  = (const float*)d_in[11];
    const float* projB  = (const float*)d_in[12];
    const float* Widk   = (const float*)d_in[13];
    const float* bidk   = (const float*)d_in[14];
    const float* idkA   = (const float*)d_in[15];
    const float* idkB   = (const float*)d_in[16];
    const float* Widv   = (const float*)d_in[17];
    const float* bidv   = (const float*)d_in[18];
    const float* idvA   = (const float*)d_in[19];
    const float* idvB   = (const float*)d_in[20];

    float* out  = (float*)d_out;
    float* kmid = out + Bb*Nn*Cc;            // k_m_id region
    float* vmid = kmid + Bb*Hh*NM*Dd;        // v_m_id region

    k_qkv_low<<<Bb*Nn, NT>>>(x, qkvA);
    k_sgemm_qkv<<<dim3(36, 80), NT>>>(x, Wqkv, bqkv, qkvB);
    k_id_small<<<Bb*NM, NT>>>(idt, idkA, idvA, Widk, bidk, idkB);
    k_sgemm_idv<<<dim3(12, 16), NT>>>(idt, Widv, bidv, idvB);
    k_apply_id<<<(Bb*Hh*NM*Dd)/NT, NT>>>(kmid, vmid);
    k_attn_m<<<Bb*Hh*NM, NT>>>(kmid, vmid);
    k_attn_s<<<Bb*Hh*NSd, NT>>>(memk, memv, vmid);
    k_route<<<Bb*Nn, NT>>>(routeW, projA);
    k_sgemm_proj<<<dim3(12, 80), NT>>>(Wproj, bproj, projB, out);
}